// round 16
// baseline (speedup 1.0000x reference)
#include <cuda_runtime.h>
#include <cuda_bf16.h>

#define U 64
#define M 8192
#define D 64
#define CHUNK 512
#define NCHUNK (M / CHUNK)   // 16
#define BLOCK 256
#define NWARP (BLOCK / 32)   // 8
#define SLOTS_PER_WARP (CHUNK / NWARP)   // 64

#define NEG_INF_F __int_as_float(0xff800000)

// Device scratch (no allocations allowed)
__device__ float g_cmax[U * NCHUNK];
__device__ float g_csum[U * NCHUNK];

// ---------------------------------------------------------------------------
// Kernel 1: scores + per-chunk softmax stats.
// CHANGE vs R14: 4 independent LDG.128 per warp-iteration (was 2), 4
// interleaved shfl chains. grid (NCHUNK, U), block 256.
// ---------------------------------------------------------------------------
__global__ void __launch_bounds__(BLOCK)
k_scores(const float* __restrict__ q,      // [U, D]
         const float* __restrict__ keys,   // [U, M, D]
         const int*   __restrict__ mask,   // [U, M] (0/1 int32)
         const float* __restrict__ tmpr,   // [U, 1]
         float* __restrict__ scores,       // [U, M]
         float* __restrict__ outp)         // [U, D] -> zeroed here
{
    __shared__ float s_s[CHUNK];
    __shared__ float s_red[NWARP];

    const int u = blockIdx.y, c = blockIdx.x;
    const int tid = threadIdx.x, lane = tid & 31, warp = tid >> 5;
    const int sub = lane & 15, half = lane >> 4;
    const int m0 = c * CHUNK;

    if (c == 0 && tid < D / 4)
        ((float4*)(outp + u * D))[tid] = make_float4(0.0f, 0.0f, 0.0f, 0.0f);

    const float4 q4 = ((const float4*)(q + u * D))[sub];

    const int base_slot = warp * SLOTS_PER_WARP;
    #pragma unroll
    for (int i = 0; i < SLOTS_PER_WARP / 8; i++) {           // 8 iterations
        const int j0 = base_slot + 8 * i + half;             // j0,+2,+4,+6
        const float4* p0 = (const float4*)(keys + ((size_t)(u * M + m0 + j0)) * D) + sub;
        const float4 a = __ldcs(p0);
        const float4 b = __ldcs(p0 + 2 * D / 4);
        const float4 d = __ldcs(p0 + 4 * D / 4);
        const float4 e = __ldcs(p0 + 6 * D / 4);
        float pa = a.x * q4.x + a.y * q4.y + a.z * q4.z + a.w * q4.w;
        float pb = b.x * q4.x + b.y * q4.y + b.z * q4.z + b.w * q4.w;
        float pd = d.x * q4.x + d.y * q4.y + d.z * q4.z + d.w * q4.w;
        float pe = e.x * q4.x + e.y * q4.y + e.z * q4.z + e.w * q4.w;
        #pragma unroll
        for (int o = 1; o < 16; o <<= 1) {
            pa += __shfl_xor_sync(0xffffffffu, pa, o);
            pb += __shfl_xor_sync(0xffffffffu, pb, o);
            pd += __shfl_xor_sync(0xffffffffu, pd, o);
            pe += __shfl_xor_sync(0xffffffffu, pe, o);
        }
        if (sub == 0) {
            s_s[j0]     = pa;
            s_s[j0 + 2] = pb;
            s_s[j0 + 4] = pd;
            s_s[j0 + 6] = pe;
        }
    }
    __syncthreads();

    const float t = tmpr[u];
    const int j2 = tid * 2;
    const float2 sv = *(const float2*)&s_s[j2];
    const int2  mk = ((const int2*)(mask + u * M + m0))[tid];
    float s0 = ((mk.x != 0) ? -1e9f : sv.x) / t;
    float s1 = ((mk.y != 0) ? -1e9f : sv.y) / t;
    ((float2*)(scores + (size_t)u * M + m0))[tid] = make_float2(s0, s1);

    float lm = fmaxf(s0, s1);
    #pragma unroll
    for (int o = 16; o > 0; o >>= 1) lm = fmaxf(lm, __shfl_xor_sync(0xffffffffu, lm, o));
    if (lane == 0) s_red[warp] = lm;
    __syncthreads();
    float cmax = s_red[0];
    #pragma unroll
    for (int w = 1; w < NWARP; w++) cmax = fmaxf(cmax, s_red[w]);
    __syncthreads();

    float ls = __expf(s0 - cmax) + __expf(s1 - cmax);
    #pragma unroll
    for (int o = 16; o > 0; o >>= 1) ls += __shfl_xor_sync(0xffffffffu, ls, o);
    if (lane == 0) s_red[warp] = ls;
    __syncthreads();
    if (tid == 0) {
        float sm = 0.0f;
        #pragma unroll
        for (int w = 0; w < NWARP; w++) sm += s_red[w];
        g_cmax[u * NCHUNK + c] = cmax;
        g_csum[u * NCHUNK + c] = sm;
    }
}

// ---------------------------------------------------------------------------
// Kernel 2: recombine -> weights, weighted memory sum + fused memories copy,
// atomicAdd epilogue.
// CHANGE vs R14: 8 independent LDG.128 batched before 8 STG.128 per
// iteration (read-MLP x2 again; fewer DRAM direction turnarounds).
// grid (NCHUNK, U), block 256.
// ---------------------------------------------------------------------------
__global__ void __launch_bounds__(BLOCK)
k_out(const float* __restrict__ mem,       // [U, M, D]
      float* __restrict__ weights,         // [U, M] (scores on entry)
      float* __restrict__ memout,          // [U, M, D]
      float* __restrict__ outp)            // [U, D] (zeroed by k_scores)
{
    __shared__ float  s_w[CHUNK];
    __shared__ float  s_stats[2];          // {gmax, inv}
    __shared__ float4 s_acc[NWARP][32];

    const int u = blockIdx.y, c = blockIdx.x;
    const int tid = threadIdx.x, lane = tid & 31, warp = tid >> 5;
    const int sub = lane & 15, half = lane >> 4;
    const int m0 = c * CHUNK;

    // ---- warp 0 only: global softmax stats (16 expf per CTA total) ----
    if (warp == 0) {
        const float cm = (lane < NCHUNK) ? g_cmax[u * NCHUNK + lane] : NEG_INF_F;
        const float cs = (lane < NCHUNK) ? g_csum[u * NCHUNK + lane] : 0.0f;
        float gm = cm;
        #pragma unroll
        for (int o = 16; o > 0; o >>= 1) gm = fmaxf(gm, __shfl_xor_sync(0xffffffffu, gm, o));
        float term = (lane < NCHUNK) ? cs * __expf(cm - gm) : 0.0f;
        #pragma unroll
        for (int o = 16; o > 0; o >>= 1) term += __shfl_xor_sync(0xffffffffu, term, o);
        if (lane == 0) {
            s_stats[0] = gm;
            s_stats[1] = 1.0f / term;
        }
    }
    __syncthreads();
    const float gmax = s_stats[0];
    const float inv  = s_stats[1];

    // ---- Phase 1: chunk weights, coalesced (scores likely L2-hot) ----
    const int j2 = tid * 2;
    const float2 sv = ((const float2*)(weights + (size_t)u * M + m0))[tid];
    const float w0 = __expf(sv.x - gmax) * inv;
    const float w1 = __expf(sv.y - gmax) * inv;
    s_w[j2]     = w0;
    s_w[j2 + 1] = w1;
    __stcs((float2*)(weights + (size_t)u * M + m0) + tid, make_float2(w0, w1));
    __syncthreads();

    // ---- Phase 2: stream memories once: weighted sum + fused copy ----
    float4 acc0 = make_float4(0.0f, 0.0f, 0.0f, 0.0f);
    float4 acc1 = make_float4(0.0f, 0.0f, 0.0f, 0.0f);
    float4 acc2 = make_float4(0.0f, 0.0f, 0.0f, 0.0f);
    float4 acc3 = make_float4(0.0f, 0.0f, 0.0f, 0.0f);
    const int base_slot = warp * SLOTS_PER_WARP;
    #pragma unroll
    for (int i = 0; i < SLOTS_PER_WARP / 16; i++) {          // 4 iterations
        const int j0 = base_slot + 16 * i + half;            // j0,+2,..,+14
        const float4* ld = (const float4*)(mem    + ((size_t)(u * M + m0 + j0)) * D) + sub;
        float4*       st = (float4*)      (memout + ((size_t)(u * M + m0 + j0)) * D) + sub;
        const int STEP = 2 * D / 4;                          // float4 units per 2 slots
        const float4 a = __ldcs(ld);
        const float4 b = __ldcs(ld + 1 * STEP);
        const float4 d = __ldcs(ld + 2 * STEP);
        const float4 e = __ldcs(ld + 3 * STEP);
        const float4 f = __ldcs(ld + 4 * STEP);
        const float4 g = __ldcs(ld + 5 * STEP);
        const float4 h = __ldcs(ld + 6 * STEP);
        const float4 k = __ldcs(ld + 7 * STEP);
        const float wa = s_w[j0];      const float wb = s_w[j0 + 2];
        const float wd = s_w[j0 + 4];  const float we = s_w[j0 + 6];
        const float wf = s_w[j0 + 8];  const float wg = s_w[j0 + 10];
        const float wh = s_w[j0 + 12]; const float wk = s_w[j0 + 14];
        acc0.x = fmaf(wa, a.x, acc0.x); acc0.y = fmaf(wa, a.y, acc0.y);
        acc0.z = fmaf(wa, a.z, acc0.z); acc0.w = fmaf(wa, a.w, acc0.w);
        acc1.x = fmaf(wb, b.x, acc1.x); acc1.y = fmaf(wb, b.y, acc1.y);
        acc1.z = fmaf(wb, b.z, acc1.z); acc1.w = fmaf(wb, b.w, acc1.w);
        acc2.x = fmaf(wd, d.x, acc2.x); acc2.y = fmaf(wd, d.y, acc2.y);
        acc2.z = fmaf(wd, d.z, acc2.z); acc2.w = fmaf(wd, d.w, acc2.w);
        acc3.x = fmaf(we, e.x, acc3.x); acc3.y = fmaf(we, e.y, acc3.y);
        acc3.z = fmaf(we, e.z, acc3.z); acc3.w = fmaf(we, e.w, acc3.w);
        acc0.x = fmaf(wf, f.x, acc0.x); acc0.y = fmaf(wf, f.y, acc0.y);
        acc0.z = fmaf(wf, f.z, acc0.z); acc0.w = fmaf(wf, f.w, acc0.w);
        acc1.x = fmaf(wg, g.x, acc1.x); acc1.y = fmaf(wg, g.y, acc1.y);
        acc1.z = fmaf(wg, g.z, acc1.z); acc1.w = fmaf(wg, g.w, acc1.w);
        acc2.x = fmaf(wh, h.x, acc2.x); acc2.y = fmaf(wh, h.y, acc2.y);
        acc2.z = fmaf(wh, h.z, acc2.z); acc2.w = fmaf(wh, h.w, acc2.w);
        acc3.x = fmaf(wk, k.x, acc3.x); acc3.y = fmaf(wk, k.y, acc3.y);
        acc3.z = fmaf(wk, k.z, acc3.z); acc3.w = fmaf(wk, k.w, acc3.w);
        __stcs(st,            a);                            // fused copy
        __stcs(st + 1 * STEP, b);
        __stcs(st + 2 * STEP, d);
        __stcs(st + 3 * STEP, e);
        __stcs(st + 4 * STEP, f);
        __stcs(st + 5 * STEP, g);
        __stcs(st + 6 * STEP, h);
        __stcs(st + 7 * STEP, k);
    }
    acc0.x += acc1.x + acc2.x + acc3.x;
    acc0.y += acc1.y + acc2.y + acc3.y;
    acc0.z += acc1.z + acc2.z + acc3.z;
    acc0.w += acc1.w + acc2.w + acc3.w;
    s_acc[warp][lane] = acc0;
    __syncthreads();

    // ---- Phase 3: chunk partial -> outputs via atomicAdd ----
    if (tid < 16) {
        float4 tsum = make_float4(0.0f, 0.0f, 0.0f, 0.0f);
        #pragma unroll
        for (int w = 0; w < NWARP; w++) {
            #pragma unroll
            for (int h = 0; h < 2; h++) {
                const float4 v = s_acc[w][h * 16 + tid];
                tsum.x += v.x; tsum.y += v.y; tsum.z += v.z; tsum.w += v.w;
            }
        }
        float* dst = outp + u * D + tid * 4;
        atomicAdd(dst + 0, tsum.x);
        atomicAdd(dst + 1, tsum.y);
        atomicAdd(dst + 2, tsum.z);
        atomicAdd(dst + 3, tsum.w);
    }
}

extern "C" void kernel_launch(void* const* d_in, const int* in_sizes, int n_in,
                              void* d_out, int out_size)
{
    const float* attention  = (const float*)d_in[0];  // [U, D]
    const float* attentions = (const float*)d_in[1];  // [U, M, D]
    const float* memories   = (const float*)d_in[2];  // [U, M, D]
    const float* tmpr       = (const float*)d_in[3];  // [U, 1]
    const int*   mask       = (const int*)  d_in[4];  // [U, M]

    float* out          = (float*)d_out;
    float* out_outputs  = out;                        // [U, D]
    float* out_weights  = out + U * D;                // [U, M]
    float* out_memories = out + U * D + U * M;        // [U, M, D]

    dim3 grid(NCHUNK, U);
    k_scores<<<grid, BLOCK>>>(attention, attentions, mask, tmpr,
                              out_weights, out_outputs);
    k_out<<<grid, BLOCK>>>(memories, out_weights, out_memories, out_outputs);
}